// round 5
// baseline (speedup 1.0000x reference)
#include <cuda_runtime.h>
#include <cuda_fp16.h>
#include <cstdint>
#include <cstddef>

// Problem dims (fixed by the reference)
static constexpr int M_DIM  = 512;    // B*S
static constexpr int K_DIM  = 4096;   // IN
static constexpr int N_DIM  = 11008;  // OUT
static constexpr int MTILE  = 128;
static constexpr int NTILE  = 128;
static constexpr int KSLAB  = 64;     // K per pipeline slab
static constexpr int NSLABS = K_DIM / KSLAB;   // 64
static constexpr int THREADS = 512;   // 16 warps: 4(m) x 4(n), 32x32 each

// fp16 copy of the activations (exact GEMM except one f32->f16 rounding)
__device__ __half g_A[M_DIM * K_DIM];   // 4 MB static scratch

// ------------------------------------------------------------------ helpers
__device__ __forceinline__ uint32_t smem_u32(const void* p) {
    uint32_t r;
    asm("{ .reg .u64 t; cvta.to.shared.u64 t, %1; cvt.u32.u64 %0, t; }"
        : "=r"(r) : "l"(p));
    return r;
}

// XOR swizzle on 128B rows (16B chunks) -> conflict-free ldmatrix
#define SWZ(o) ((o) ^ (((o) >> 3) & 0x70))

__device__ __forceinline__ void ldsm_x4(uint32_t& r0, uint32_t& r1,
                                        uint32_t& r2, uint32_t& r3, uint32_t a) {
    asm volatile("ldmatrix.sync.aligned.m8n8.x4.shared.b16 {%0,%1,%2,%3}, [%4];"
                 : "=r"(r0), "=r"(r1), "=r"(r2), "=r"(r3) : "r"(a));
}

__device__ __forceinline__ void mma16816(float* d, const uint32_t* a,
                                         uint32_t b0, uint32_t b1) {
    asm volatile(
        "mma.sync.aligned.m16n8k16.row.col.f32.f16.f16.f32 "
        "{%0,%1,%2,%3}, {%4,%5,%6,%7}, {%8,%9}, {%0,%1,%2,%3};"
        : "+f"(d[0]), "+f"(d[1]), "+f"(d[2]), "+f"(d[3])
        : "r"(a[0]), "r"(a[1]), "r"(a[2]), "r"(a[3]), "r"(b0), "r"(b1));
}

// ------------------------------------------------------------------ SMEM layout
// stage p at p*32768: A tile (128 rows x 128B) then W tile (128 rows x 128B)
static constexpr int STAGE_BYTES = 32768;
static constexpr int W_OFF       = 16384;
static constexpr int SMEM_BYTES  = 2 * STAGE_BYTES + 1024;  // + align slack

// ------------------------------------------------------------------ kernels
__global__ void convert_A_kernel(const float* __restrict__ in) {
    int n4 = (M_DIM * K_DIM) / 4;
    int i = blockIdx.x * blockDim.x + threadIdx.x;
    if (i >= n4) return;
    float4 v = reinterpret_cast<const float4*>(in)[i];
    __half2 h0 = __floats2half2_rn(v.x, v.y);
    __half2 h1 = __floats2half2_rn(v.z, v.w);
    uint2 u;
    u.x = *reinterpret_cast<uint32_t*>(&h0);
    u.y = *reinterpret_cast<uint32_t*>(&h1);
    reinterpret_cast<uint2*>(g_A)[i] = u;
}

__global__ void __launch_bounds__(THREADS, 1)
qlinear_hmma_kernel(const int4* __restrict__ W, const float* __restrict__ scale,
                    const float* __restrict__ bias, float* __restrict__ out) {
    extern __shared__ char smem_raw[];
    const uint32_t smem = (smem_u32(smem_raw) + 1023u) & ~1023u;

    const int tid  = threadIdx.x;
    const int wid  = tid >> 5;
    const int lane = tid & 31;
    const int wm   = wid >> 2;          // 0..3 : 32-row M strip
    const int wn   = wid & 3;           // 0..3 : 32-col N strip
    const int m0   = blockIdx.x * MTILE;    // m fastest -> weight L2 reuse
    const int n0   = blockIdx.y * NTILE;

    const __half* Abase = g_A + (size_t)m0 * K_DIM;
    const size_t  wrow  = (size_t)K_DIM / 4;   // int4s per weight row

    float acc[2][4][4];
#pragma unroll
    for (int i = 0; i < 2; i++)
#pragma unroll
        for (int j = 0; j < 4; j++)
#pragma unroll
            for (int e = 0; e < 4; e++) acc[i][j][e] = 0.f;

    // per-thread W staging (regs reused every slab)
    int4 wq[4];

    // ---- prologue: W(0) -> regs, A(0) -> smem stage 0 -------------------
#pragma unroll
    for (int i = 0; i < 4; i++) {
        int li = i * 512 + tid, r = li >> 4, cg = li & 15;
        wq[i] = W[(size_t)(n0 + r) * wrow + cg];
    }
#pragma unroll
    for (int i = 0; i < 2; i++) {
        int li = i * 512 + tid, r = li >> 3, c = li & 7;
        const __half* src = Abase + (size_t)r * K_DIM + c * 8;
        uint32_t dst = smem + SWZ(r * 128 + c * 16);
        asm volatile("cp.async.cg.shared.global [%0], [%1], 16;" :: "r"(dst), "l"(src));
    }
    asm volatile("cp.async.commit_group;" ::: "memory");

    // ---- main loop ------------------------------------------------------
#pragma unroll 1
    for (int s = 0; s < NSLABS; s++) {
        const int p = s & 1;
        const uint32_t a_sm = smem + p * STAGE_BYTES;
        const uint32_t w_sm = a_sm + W_OFF;

        // dequant W(s): exact (q-128) in fp16 -> STS
#pragma unroll
        for (int i = 0; i < 4; i++) {
            int li = i * 512 + tid, r = li >> 4, cg = li & 15;
            __half2 h0 = __halves2half2(__int2half_rn(wq[i].x - 128),
                                        __int2half_rn(wq[i].y - 128));
            __half2 h1 = __halves2half2(__int2half_rn(wq[i].z - 128),
                                        __int2half_rn(wq[i].w - 128));
            uint32_t u0 = *reinterpret_cast<uint32_t*>(&h0);
            uint32_t u1 = *reinterpret_cast<uint32_t*>(&h1);
            uint32_t dst = w_sm + SWZ(r * 128 + cg * 8);
            asm volatile("st.shared.v2.b32 [%0], {%1, %2};"
                         :: "r"(dst), "r"(u0), "r"(u1) : "memory");
        }

        asm volatile("cp.async.wait_group 0;" ::: "memory");   // A(s) arrived
        __syncthreads();                                       // stage p ready

        // prefetch next slab (overlaps compute below)
        if (s + 1 < NSLABS) {
#pragma unroll
            for (int i = 0; i < 4; i++) {
                int li = i * 512 + tid, r = li >> 4, cg = li & 15;
                wq[i] = W[(size_t)(n0 + r) * wrow + (s + 1) * (KSLAB / 4) + cg];
            }
#pragma unroll
            for (int i = 0; i < 2; i++) {
                int li = i * 512 + tid, r = li >> 3, c = li & 7;
                const __half* src = Abase + (size_t)r * K_DIM + (s + 1) * KSLAB + c * 8;
                uint32_t dst = smem + (p ^ 1) * STAGE_BYTES + SWZ(r * 128 + c * 16);
                asm volatile("cp.async.cg.shared.global [%0], [%1], 16;"
                             :: "r"(dst), "l"(src));
            }
            asm volatile("cp.async.commit_group;" ::: "memory");
        }

        // compute slab s: 4 k-steps of 16
#pragma unroll
        for (int ks = 0; ks < 4; ks++) {
            const int chunk = ks * 2 + (lane >> 4);
            uint32_t a[2][4];
#pragma unroll
            for (int mt = 0; mt < 2; mt++) {
                int row = wm * 32 + mt * 16 + (lane & 15);
                ldsm_x4(a[mt][0], a[mt][1], a[mt][2], a[mt][3],
                        a_sm + SWZ(row * 128 + chunk * 16));
            }
            uint32_t b[4][2];
#pragma unroll
            for (int j = 0; j < 2; j++) {
                int row = wn * 32 + j * 16 + (lane & 15);
                uint32_t t0, t1, t2, t3;
                ldsm_x4(t0, t1, t2, t3, w_sm + SWZ(row * 128 + chunk * 16));
                b[j * 2 + 0][0] = t0;  b[j * 2 + 1][0] = t1;
                b[j * 2 + 0][1] = t2;  b[j * 2 + 1][1] = t3;
            }
#pragma unroll
            for (int mt = 0; mt < 2; mt++)
#pragma unroll
                for (int nt = 0; nt < 4; nt++)
                    mma16816(acc[mt][nt], a[mt], b[nt][0], b[nt][1]);
        }
    }

    // ---- epilogue: scale*acc + bias -> out ------------------------------
    const int ncb = n0 + wn * 32;
    float sc[4][2], bs[4][2];
#pragma unroll
    for (int nt = 0; nt < 4; nt++) {
#pragma unroll
        for (int e = 0; e < 2; e++) {
            int col = ncb + nt * 8 + (lane & 3) * 2 + e;
            sc[nt][e] = __ldg(&scale[col]);
            bs[nt][e] = __ldg(&bias[col]);
        }
    }
#pragma unroll
    for (int mt = 0; mt < 2; mt++) {
        int row = m0 + wm * 32 + mt * 16 + (lane >> 2);
#pragma unroll
        for (int nt = 0; nt < 4; nt++) {
            int col = ncb + nt * 8 + (lane & 3) * 2;
            float2 v0, v1;
            v0.x = acc[mt][nt][0] * sc[nt][0] + bs[nt][0];
            v0.y = acc[mt][nt][1] * sc[nt][1] + bs[nt][1];
            v1.x = acc[mt][nt][2] * sc[nt][0] + bs[nt][0];
            v1.y = acc[mt][nt][3] * sc[nt][1] + bs[nt][1];
            *reinterpret_cast<float2*>(out + (size_t)row * N_DIM + col)       = v0;
            *reinterpret_cast<float2*>(out + (size_t)(row + 8) * N_DIM + col) = v1;
        }
    }
}

// ------------------------------------------------------------------ launch
extern "C" void kernel_launch(void* const* d_in, const int* in_sizes, int n_in,
                              void* d_out, int out_size) {
    (void)in_sizes; (void)n_in; (void)out_size;
    const float* input = (const float*)d_in[0];
    const int4*  W     = (const int4*)d_in[1];
    const float* scale = (const float*)d_in[2];
    const float* bias  = (const float*)d_in[3];
    float* out = (float*)d_out;

    convert_A_kernel<<<(M_DIM * K_DIM / 4 + 255) / 256, 256>>>(input);

    cudaFuncSetAttribute(qlinear_hmma_kernel,
                         cudaFuncAttributeMaxDynamicSharedMemorySize, SMEM_BYTES);
    dim3 grid(M_DIM / MTILE, N_DIM / NTILE);   // m fastest: weight L2 reuse
    qlinear_hmma_kernel<<<grid, THREADS, SMEM_BYTES>>>(W, scale, bias, out);
}

// round 6
// speedup vs baseline: 1.2329x; 1.2329x over previous
#include <cuda_runtime.h>
#include <cuda_fp16.h>
#include <cstdint>
#include <cstddef>

// Problem dims (fixed by the reference)
static constexpr int M_DIM  = 512;    // B*S
static constexpr int K_DIM  = 4096;   // IN
static constexpr int N_DIM  = 11008;  // OUT
static constexpr int MTILE  = 128;
static constexpr int NTILE  = 64;     // smaller N tile -> 2 CTAs/SM
static constexpr int KSLAB  = 64;     // K per pipeline slab
static constexpr int NSLABS = K_DIM / KSLAB;   // 64
static constexpr int THREADS = 256;   // 8 warps: 4(m) x 2(n), 32x32 each

// fp16 copy of the activations (exact GEMM except one f32->f16 rounding)
__device__ __half g_A[M_DIM * K_DIM];   // 4 MB static scratch

// ------------------------------------------------------------------ helpers
__device__ __forceinline__ uint32_t smem_u32(const void* p) {
    uint32_t r;
    asm("{ .reg .u64 t; cvta.to.shared.u64 t, %1; cvt.u32.u64 %0, t; }"
        : "=r"(r) : "l"(p));
    return r;
}

// XOR swizzle on 128B rows (16B chunks) -> conflict-free ldmatrix
#define SWZ(o) ((o) ^ (((o) >> 3) & 0x70))

__device__ __forceinline__ void ldsm_x4(uint32_t& r0, uint32_t& r1,
                                        uint32_t& r2, uint32_t& r3, uint32_t a) {
    asm volatile("ldmatrix.sync.aligned.m8n8.x4.shared.b16 {%0,%1,%2,%3}, [%4];"
                 : "=r"(r0), "=r"(r1), "=r"(r2), "=r"(r3) : "r"(a));
}

__device__ __forceinline__ void mma16816(float* d, const uint32_t* a,
                                         uint32_t b0, uint32_t b1) {
    asm volatile(
        "mma.sync.aligned.m16n8k16.row.col.f32.f16.f16.f32 "
        "{%0,%1,%2,%3}, {%4,%5,%6,%7}, {%8,%9}, {%0,%1,%2,%3};"
        : "+f"(d[0]), "+f"(d[1]), "+f"(d[2]), "+f"(d[3])
        : "r"(a[0]), "r"(a[1]), "r"(a[2]), "r"(a[3]), "r"(b0), "r"(b1));
}

// ------------------------------------------------------------------ SMEM layout
// stage p at p*24576: A tile (128 rows x 128B) then W tile (64 rows x 128B)
static constexpr int STAGE_BYTES = 24576;
static constexpr int W_OFF       = 16384;
static constexpr int SMEM_BYTES  = 2 * STAGE_BYTES + 1024;  // 50176 (fits 2/SM)

// ------------------------------------------------------------------ kernels
__global__ void convert_A_kernel(const float* __restrict__ in) {
    int n4 = (M_DIM * K_DIM) / 4;
    int i = blockIdx.x * blockDim.x + threadIdx.x;
    if (i >= n4) return;
    float4 v = reinterpret_cast<const float4*>(in)[i];
    __half2 h0 = __floats2half2_rn(v.x, v.y);
    __half2 h1 = __floats2half2_rn(v.z, v.w);
    uint2 u;
    u.x = *reinterpret_cast<uint32_t*>(&h0);
    u.y = *reinterpret_cast<uint32_t*>(&h1);
    reinterpret_cast<uint2*>(g_A)[i] = u;
}

__global__ void __launch_bounds__(THREADS, 2)
qlinear_hmma_kernel(const int4* __restrict__ W, const float* __restrict__ scale,
                    const float* __restrict__ bias, float* __restrict__ out) {
    extern __shared__ char smem_raw[];
    const uint32_t smem = (smem_u32(smem_raw) + 1023u) & ~1023u;

    const int tid  = threadIdx.x;
    const int wid  = tid >> 5;
    const int lane = tid & 31;
    const int wm   = wid >> 1;          // 0..3 : 32-row M strip
    const int wn   = wid & 1;           // 0..1 : 32-col N strip
    const int m0   = blockIdx.x * MTILE;    // m fastest -> weight L2 reuse
    const int n0   = blockIdx.y * NTILE;

    const __half* Abase = g_A + (size_t)m0 * K_DIM;
    const size_t  wrow  = (size_t)K_DIM / 4;   // int4s per weight row

    float acc[2][4][4];
#pragma unroll
    for (int i = 0; i < 2; i++)
#pragma unroll
        for (int j = 0; j < 4; j++)
#pragma unroll
            for (int e = 0; e < 4; e++) acc[i][j][e] = 0.f;

    // per-thread W staging (regs reused every slab): 64 rows x 16 int4
    int4 wq[4];

    // ---- prologue: W(0) -> regs, A(0) -> smem stage 0 -------------------
#pragma unroll
    for (int i = 0; i < 4; i++) {
        int li = i * 256 + tid, r = li >> 4, cg = li & 15;
        wq[i] = W[(size_t)(n0 + r) * wrow + cg];
    }
#pragma unroll
    for (int i = 0; i < 4; i++) {
        int li = i * 256 + tid, r = li >> 3, c = li & 7;
        const __half* src = Abase + (size_t)r * K_DIM + c * 8;
        uint32_t dst = smem + SWZ(r * 128 + c * 16);
        asm volatile("cp.async.cg.shared.global [%0], [%1], 16;" :: "r"(dst), "l"(src));
    }
    asm volatile("cp.async.commit_group;" ::: "memory");

    // ---- main loop ------------------------------------------------------
#pragma unroll 1
    for (int s = 0; s < NSLABS; s++) {
        const int p = s & 1;
        const uint32_t a_sm = smem + p * STAGE_BYTES;
        const uint32_t w_sm = a_sm + W_OFF;

        // dequant W(s): exact (q-128) in fp16 -> STS
#pragma unroll
        for (int i = 0; i < 4; i++) {
            int li = i * 256 + tid, r = li >> 4, cg = li & 15;
            __half2 h0 = __halves2half2(__int2half_rn(wq[i].x - 128),
                                        __int2half_rn(wq[i].y - 128));
            __half2 h1 = __halves2half2(__int2half_rn(wq[i].z - 128),
                                        __int2half_rn(wq[i].w - 128));
            uint32_t u0 = *reinterpret_cast<uint32_t*>(&h0);
            uint32_t u1 = *reinterpret_cast<uint32_t*>(&h1);
            uint32_t dst = w_sm + SWZ(r * 128 + cg * 8);
            asm volatile("st.shared.v2.b32 [%0], {%1, %2};"
                         :: "r"(dst), "r"(u0), "r"(u1) : "memory");
        }

        asm volatile("cp.async.wait_group 0;" ::: "memory");   // A(s) arrived
        __syncthreads();                                       // stage p ready

        // prefetch next slab (overlaps compute below)
        if (s + 1 < NSLABS) {
#pragma unroll
            for (int i = 0; i < 4; i++) {
                int li = i * 256 + tid, r = li >> 4, cg = li & 15;
                wq[i] = W[(size_t)(n0 + r) * wrow + (s + 1) * (KSLAB / 4) + cg];
            }
#pragma unroll
            for (int i = 0; i < 4; i++) {
                int li = i * 256 + tid, r = li >> 3, c = li & 7;
                const __half* src = Abase + (size_t)r * K_DIM + (s + 1) * KSLAB + c * 8;
                uint32_t dst = smem + (p ^ 1) * STAGE_BYTES + SWZ(r * 128 + c * 16);
                asm volatile("cp.async.cg.shared.global [%0], [%1], 16;"
                             :: "r"(dst), "l"(src));
            }
            asm volatile("cp.async.commit_group;" ::: "memory");
        }

        // compute slab s: 4 k-steps of 16
#pragma unroll
        for (int ks = 0; ks < 4; ks++) {
            const int chunk = ks * 2 + (lane >> 4);
            uint32_t a[2][4];
#pragma unroll
            for (int mt = 0; mt < 2; mt++) {
                int row = wm * 32 + mt * 16 + (lane & 15);
                ldsm_x4(a[mt][0], a[mt][1], a[mt][2], a[mt][3],
                        a_sm + SWZ(row * 128 + chunk * 16));
            }
            uint32_t b[4][2];
#pragma unroll
            for (int j = 0; j < 2; j++) {
                int row = wn * 32 + j * 16 + (lane & 15);
                uint32_t t0, t1, t2, t3;
                ldsm_x4(t0, t1, t2, t3, w_sm + SWZ(row * 128 + chunk * 16));
                b[j * 2 + 0][0] = t0;  b[j * 2 + 1][0] = t1;
                b[j * 2 + 0][1] = t2;  b[j * 2 + 1][1] = t3;
            }
#pragma unroll
            for (int mt = 0; mt < 2; mt++)
#pragma unroll
                for (int nt = 0; nt < 4; nt++)
                    mma16816(acc[mt][nt], a[mt], b[nt][0], b[nt][1]);
        }
    }

    // ---- epilogue: scale*acc + bias -> out ------------------------------
    const int ncb = n0 + wn * 32;
    float sc[4][2], bs[4][2];
#pragma unroll
    for (int nt = 0; nt < 4; nt++) {
#pragma unroll
        for (int e = 0; e < 2; e++) {
            int col = ncb + nt * 8 + (lane & 3) * 2 + e;
            sc[nt][e] = __ldg(&scale[col]);
            bs[nt][e] = __ldg(&bias[col]);
        }
    }
#pragma unroll
    for (int mt = 0; mt < 2; mt++) {
        int row = m0 + wm * 32 + mt * 16 + (lane >> 2);
#pragma unroll
        for (int nt = 0; nt < 4; nt++) {
            int col = ncb + nt * 8 + (lane & 3) * 2;
            float2 v0, v1;
            v0.x = acc[mt][nt][0] * sc[nt][0] + bs[nt][0];
            v0.y = acc[mt][nt][1] * sc[nt][1] + bs[nt][1];
            v1.x = acc[mt][nt][2] * sc[nt][0] + bs[nt][0];
            v1.y = acc[mt][nt][3] * sc[nt][1] + bs[nt][1];
            *reinterpret_cast<float2*>(out + (size_t)row * N_DIM + col)       = v0;
            *reinterpret_cast<float2*>(out + (size_t)(row + 8) * N_DIM + col) = v1;
        }
    }
}

// ------------------------------------------------------------------ launch
extern "C" void kernel_launch(void* const* d_in, const int* in_sizes, int n_in,
                              void* d_out, int out_size) {
    (void)in_sizes; (void)n_in; (void)out_size;
    const float* input = (const float*)d_in[0];
    const int4*  W     = (const int4*)d_in[1];
    const float* scale = (const float*)d_in[2];
    const float* bias  = (const float*)d_in[3];
    float* out = (float*)d_out;

    convert_A_kernel<<<(M_DIM * K_DIM / 4 + 255) / 256, 256>>>(input);

    cudaFuncSetAttribute(qlinear_hmma_kernel,
                         cudaFuncAttributeMaxDynamicSharedMemorySize, SMEM_BYTES);
    dim3 grid(M_DIM / MTILE, N_DIM / NTILE);   // m fastest: weight L2 reuse
    qlinear_hmma_kernel<<<grid, THREADS, SMEM_BYTES>>>(W, scale, bias, out);
}

// round 7
// speedup vs baseline: 1.2792x; 1.0375x over previous
#include <cuda_runtime.h>
#include <cuda_fp16.h>
#include <cstdint>
#include <cstddef>

// Problem dims (fixed by the reference)
static constexpr int M_DIM  = 512;    // B*S
static constexpr int K_DIM  = 4096;   // IN
static constexpr int N_DIM  = 11008;  // OUT
static constexpr int MTILE  = 128;
static constexpr int NTILE  = 64;     // 2 CTAs/SM
static constexpr int KSLAB  = 64;     // K per pipeline slab
static constexpr int NSLABS = K_DIM / KSLAB;   // 64
static constexpr int THREADS = 256;   // 8 warps: 4(m) x 2(n), 32x32 each

// fp16 copy of the activations (exact GEMM except one f32->f16 rounding)
__device__ __half g_A[M_DIM * K_DIM];   // 4 MB static scratch

// ------------------------------------------------------------------ helpers
__device__ __forceinline__ uint32_t smem_u32(const void* p) {
    uint32_t r;
    asm("{ .reg .u64 t; cvta.to.shared.u64 t, %1; cvt.u32.u64 %0, t; }"
        : "=r"(r) : "l"(p));
    return r;
}

// XOR swizzle on 128B rows (16B chunks) -> conflict-free ldmatrix
#define SWZ(o) ((o) ^ (((o) >> 3) & 0x70))

__device__ __forceinline__ void ldsm_x4(uint32_t& r0, uint32_t& r1,
                                        uint32_t& r2, uint32_t& r3, uint32_t a) {
    asm volatile("ldmatrix.sync.aligned.m8n8.x4.shared.b16 {%0,%1,%2,%3}, [%4];"
                 : "=r"(r0), "=r"(r1), "=r"(r2), "=r"(r3) : "r"(a));
}

__device__ __forceinline__ void mma16816(float* d, const uint32_t* a,
                                         uint32_t b0, uint32_t b1) {
    asm volatile(
        "mma.sync.aligned.m16n8k16.row.col.f32.f16.f16.f32 "
        "{%0,%1,%2,%3}, {%4,%5,%6,%7}, {%8,%9}, {%0,%1,%2,%3};"
        : "+f"(d[0]), "+f"(d[1]), "+f"(d[2]), "+f"(d[3])
        : "r"(a[0]), "r"(a[1]), "r"(a[2]), "r"(a[3]), "r"(b0), "r"(b1));
}

// ------------------------------------------------------------------ SMEM layout
// stage p at p*24576: A tile (128 rows x 128B) then W tile (64 rows x 128B)
static constexpr int STAGE_BYTES = 24576;
static constexpr int W_OFF       = 16384;
static constexpr int SMEM_BYTES  = 2 * STAGE_BYTES + 1024;  // 50176 (fits 2/SM)

// ------------------------------------------------------------------ kernels
__global__ void convert_A_kernel(const float* __restrict__ in) {
    int n4 = (M_DIM * K_DIM) / 4;
    int i = blockIdx.x * blockDim.x + threadIdx.x;
    if (i >= n4) return;
    float4 v = reinterpret_cast<const float4*>(in)[i];
    __half2 h0 = __floats2half2_rn(v.x, v.y);
    __half2 h1 = __floats2half2_rn(v.z, v.w);
    uint2 u;
    u.x = *reinterpret_cast<uint32_t*>(&h0);
    u.y = *reinterpret_cast<uint32_t*>(&h1);
    reinterpret_cast<uint2*>(g_A)[i] = u;
}

// dequant W slab held in wq regs -> fp16 STS into stage buffer (exact q-128)
__device__ __forceinline__ void dequant_sts(const int4* wq, uint32_t w_sm, int tid) {
#pragma unroll
    for (int i = 0; i < 4; i++) {
        int li = i * 256 + tid, r = li >> 4, cg = li & 15;
        __half2 h0 = __halves2half2(__int2half_rn(wq[i].x - 128),
                                    __int2half_rn(wq[i].y - 128));
        __half2 h1 = __halves2half2(__int2half_rn(wq[i].z - 128),
                                    __int2half_rn(wq[i].w - 128));
        uint32_t u0 = *reinterpret_cast<uint32_t*>(&h0);
        uint32_t u1 = *reinterpret_cast<uint32_t*>(&h1);
        uint32_t dst = w_sm + SWZ(r * 128 + cg * 8);
        asm volatile("st.shared.v2.b32 [%0], {%1, %2};"
                     :: "r"(dst), "r"(u0), "r"(u1) : "memory");
    }
}

// issue A-slab cp.async into a stage buffer
__device__ __forceinline__ void issue_A(const __half* Abase, int s, uint32_t a_sm,
                                        int tid) {
#pragma unroll
    for (int i = 0; i < 4; i++) {
        int li = i * 256 + tid, r = li >> 3, c = li & 7;
        const __half* src = Abase + (size_t)r * K_DIM + s * KSLAB + c * 8;
        uint32_t dst = a_sm + SWZ(r * 128 + c * 16);
        asm volatile("cp.async.cg.shared.global [%0], [%1], 16;" :: "r"(dst), "l"(src));
    }
    asm volatile("cp.async.commit_group;" ::: "memory");
}

__global__ void __launch_bounds__(THREADS, 2)
qlinear_hmma_kernel(const int4* __restrict__ W, const float* __restrict__ scale,
                    const float* __restrict__ bias, float* __restrict__ out) {
    extern __shared__ char smem_raw[];
    const uint32_t smem = (smem_u32(smem_raw) + 1023u) & ~1023u;

    const int tid  = threadIdx.x;
    const int wid  = tid >> 5;
    const int lane = tid & 31;
    const int wm   = wid >> 1;          // 0..3 : 32-row M strip
    const int wn   = wid & 1;           // 0..1 : 32-col N strip
    const int m0   = blockIdx.x * MTILE;    // m fastest -> weight L2 reuse
    const int n0   = blockIdx.y * NTILE;

    const __half* Abase = g_A + (size_t)m0 * K_DIM;
    const size_t  wrow  = (size_t)K_DIM / 4;   // int4s per weight row

    float acc[2][4][4];
#pragma unroll
    for (int i = 0; i < 2; i++)
#pragma unroll
        for (int j = 0; j < 4; j++)
#pragma unroll
            for (int e = 0; e < 4; e++) acc[i][j][e] = 0.f;

    // per-thread W staging regs
    int4 wq[4];

    // ---- prologue -------------------------------------------------------
    // W(0) -> wq -> STS stage 0 (visibility ordered by sync at iter 0)
#pragma unroll
    for (int i = 0; i < 4; i++) {
        int li = i * 256 + tid, r = li >> 4, cg = li & 15;
        wq[i] = W[(size_t)(n0 + r) * wrow + cg];
    }
    issue_A(Abase, 0, smem, tid);                 // A(0) -> stage 0
    dequant_sts(wq, smem + W_OFF, tid);           // W(0) -> stage 0
    // W(1) -> wq (consumed at iter 0 post-sync)
#pragma unroll
    for (int i = 0; i < 4; i++) {
        int li = i * 256 + tid, r = li >> 4, cg = li & 15;
        wq[i] = W[(size_t)(n0 + r) * wrow + (KSLAB / 4) + cg];
    }

    // ---- main loop ------------------------------------------------------
#pragma unroll 1
    for (int s = 0; s < NSLABS; s++) {
        const int p = s & 1;
        const uint32_t a_sm = smem + p * STAGE_BYTES;
        const uint32_t w_sm = a_sm + W_OFF;

        asm volatile("cp.async.wait_group 0;" ::: "memory");   // A(s) arrived
        __syncthreads();   // stage p fully ready; stage p^1 free (readers done)

        // All prefetch work for s+1 is issued here, overlapping compute(s):
        //  - cp.async A(s+1) into p^1
        //  - dequant-STS W(s+1) (in wq) into p^1 (visible at sync(s+1))
        //  - LDG W(s+2) -> wq (latency hidden by compute(s) + compute(s+1))
        if (s + 1 < NSLABS) {
            issue_A(Abase, s + 1, smem + (p ^ 1) * STAGE_BYTES, tid);
            dequant_sts(wq, smem + (p ^ 1) * STAGE_BYTES + W_OFF, tid);
            if (s + 2 < NSLABS) {
#pragma unroll
                for (int i = 0; i < 4; i++) {
                    int li = i * 256 + tid, r = li >> 4, cg = li & 15;
                    wq[i] = W[(size_t)(n0 + r) * wrow + (s + 2) * (KSLAB / 4) + cg];
                }
            }
        }

        // compute slab s: 4 k-steps of 16
#pragma unroll
        for (int ks = 0; ks < 4; ks++) {
            const int chunk = ks * 2 + (lane >> 4);
            uint32_t a[2][4];
#pragma unroll
            for (int mt = 0; mt < 2; mt++) {
                int row = wm * 32 + mt * 16 + (lane & 15);
                ldsm_x4(a[mt][0], a[mt][1], a[mt][2], a[mt][3],
                        a_sm + SWZ(row * 128 + chunk * 16));
            }
            uint32_t b[4][2];
#pragma unroll
            for (int j = 0; j < 2; j++) {
                int row = wn * 32 + j * 16 + (lane & 15);
                uint32_t t0, t1, t2, t3;
                ldsm_x4(t0, t1, t2, t3, w_sm + SWZ(row * 128 + chunk * 16));
                b[j * 2 + 0][0] = t0;  b[j * 2 + 1][0] = t1;
                b[j * 2 + 0][1] = t2;  b[j * 2 + 1][1] = t3;
            }
#pragma unroll
            for (int mt = 0; mt < 2; mt++)
#pragma unroll
                for (int nt = 0; nt < 4; nt++)
                    mma16816(acc[mt][nt], a[mt], b[nt][0], b[nt][1]);
        }
    }

    // ---- epilogue: scale*acc + bias -> out ------------------------------
    const int ncb = n0 + wn * 32;
    float sc[4][2], bs[4][2];
#pragma unroll
    for (int nt = 0; nt < 4; nt++) {
#pragma unroll
        for (int e = 0; e < 2; e++) {
            int col = ncb + nt * 8 + (lane & 3) * 2 + e;
            sc[nt][e] = __ldg(&scale[col]);
            bs[nt][e] = __ldg(&bias[col]);
        }
    }
#pragma unroll
    for (int mt = 0; mt < 2; mt++) {
        int row = m0 + wm * 32 + mt * 16 + (lane >> 2);
#pragma unroll
        for (int nt = 0; nt < 4; nt++) {
            int col = ncb + nt * 8 + (lane & 3) * 2;
            float2 v0, v1;
            v0.x = acc[mt][nt][0] * sc[nt][0] + bs[nt][0];
            v0.y = acc[mt][nt][1] * sc[nt][1] + bs[nt][1];
            v1.x = acc[mt][nt][2] * sc[nt][0] + bs[nt][0];
            v1.y = acc[mt][nt][3] * sc[nt][1] + bs[nt][1];
            *reinterpret_cast<float2*>(out + (size_t)row * N_DIM + col)       = v0;
            *reinterpret_cast<float2*>(out + (size_t)(row + 8) * N_DIM + col) = v1;
        }
    }
}

// ------------------------------------------------------------------ launch
extern "C" void kernel_launch(void* const* d_in, const int* in_sizes, int n_in,
                              void* d_out, int out_size) {
    (void)in_sizes; (void)n_in; (void)out_size;
    const float* input = (const float*)d_in[0];
    const int4*  W     = (const int4*)d_in[1];
    const float* scale = (const float*)d_in[2];
    const float* bias  = (const float*)d_in[3];
    float* out = (float*)d_out;

    convert_A_kernel<<<(M_DIM * K_DIM / 4 + 255) / 256, 256>>>(input);

    cudaFuncSetAttribute(qlinear_hmma_kernel,
                         cudaFuncAttributeMaxDynamicSharedMemorySize, SMEM_BYTES);
    dim3 grid(M_DIM / MTILE, N_DIM / NTILE);   // m fastest: weight L2 reuse
    qlinear_hmma_kernel<<<grid, THREADS, SMEM_BYTES>>>(W, scale, bias, out);
}

// round 8
// speedup vs baseline: 1.2820x; 1.0022x over previous
#include <cuda_runtime.h>
#include <cuda_fp16.h>
#include <cstdint>
#include <cstddef>

// Problem dims (fixed by the reference)
static constexpr int M_DIM  = 512;    // B*S
static constexpr int K_DIM  = 4096;   // IN
static constexpr int N_DIM  = 11008;  // OUT
static constexpr int MTILE  = 128;
static constexpr int NTILE  = 64;     // 2 CTAs/SM
static constexpr int KSLAB  = 128;    // K per pipeline slab (2 halves of 64)
static constexpr int NSLABS = K_DIM / KSLAB;   // 32
static constexpr int THREADS = 256;   // 8 warps: 4(m) x 2(n), 32x32 each

// fp16 copy of the activations (exact GEMM except one f32->f16 rounding)
__device__ __half g_A[M_DIM * K_DIM];   // 4 MB static scratch

// ------------------------------------------------------------------ helpers
__device__ __forceinline__ uint32_t smem_u32(const void* p) {
    uint32_t r;
    asm("{ .reg .u64 t; cvta.to.shared.u64 t, %1; cvt.u32.u64 %0, t; }"
        : "=r"(r) : "l"(p));
    return r;
}

// XOR swizzle on 128B rows (16B chunks) -> conflict-free ldmatrix
#define SWZ(o) ((o) ^ (((o) >> 3) & 0x70))

__device__ __forceinline__ void ldsm_x4(uint32_t& r0, uint32_t& r1,
                                        uint32_t& r2, uint32_t& r3, uint32_t a) {
    asm volatile("ldmatrix.sync.aligned.m8n8.x4.shared.b16 {%0,%1,%2,%3}, [%4];"
                 : "=r"(r0), "=r"(r1), "=r"(r2), "=r"(r3) : "r"(a));
}

__device__ __forceinline__ void mma16816(float* d, const uint32_t* a,
                                         uint32_t b0, uint32_t b1) {
    asm volatile(
        "mma.sync.aligned.m16n8k16.row.col.f32.f16.f16.f32 "
        "{%0,%1,%2,%3}, {%4,%5,%6,%7}, {%8,%9}, {%0,%1,%2,%3};"
        : "+f"(d[0]), "+f"(d[1]), "+f"(d[2]), "+f"(d[3])
        : "r"(a[0]), "r"(a[1]), "r"(a[2]), "r"(a[3]), "r"(b0), "r"(b1));
}

// ------------------------------------------------------------------ SMEM layout
// stage p at p*49152:
//   A: two 16KB k-half panels (128 rows x 128B, swizzled)   [0, 32768)
//   W: two  8KB k-half panels ( 64 rows x 128B, swizzled)   [32768, 49152)
static constexpr int A_HALF      = 16384;
static constexpr int W_BASE      = 32768;
static constexpr int W_HALF      = 8192;
static constexpr int STAGE_BYTES = 49152;
static constexpr int SMEM_BYTES  = 2 * STAGE_BYTES + 1024;   // 99328: 2 CTAs/SM

// ------------------------------------------------------------------ kernels
__global__ void convert_A_kernel(const float* __restrict__ in) {
    int n4 = (M_DIM * K_DIM) / 4;
    int i = blockIdx.x * blockDim.x + threadIdx.x;
    if (i >= n4) return;
    float4 v = reinterpret_cast<const float4*>(in)[i];
    __half2 h0 = __floats2half2_rn(v.x, v.y);
    __half2 h1 = __floats2half2_rn(v.z, v.w);
    uint2 u;
    u.x = *reinterpret_cast<uint32_t*>(&h0);
    u.y = *reinterpret_cast<uint32_t*>(&h1);
    reinterpret_cast<uint2*>(g_A)[i] = u;
}

// dequant W half-slab held in wq regs -> fp16 STS into an 8KB W panel
__device__ __forceinline__ void dequant_sts(const int4* wq, uint32_t w_panel, int tid) {
#pragma unroll
    for (int i = 0; i < 4; i++) {
        int li = i * 256 + tid, r = li >> 4, cg = li & 15;
        __half2 h0 = __halves2half2(__int2half_rn(wq[i].x - 128),
                                    __int2half_rn(wq[i].y - 128));
        __half2 h1 = __halves2half2(__int2half_rn(wq[i].z - 128),
                                    __int2half_rn(wq[i].w - 128));
        uint32_t u0 = *reinterpret_cast<uint32_t*>(&h0);
        uint32_t u1 = *reinterpret_cast<uint32_t*>(&h1);
        uint32_t dst = w_panel + SWZ(r * 128 + cg * 8);
        asm volatile("st.shared.v2.b32 [%0], {%1, %2};"
                     :: "r"(dst), "r"(u0), "r"(u1) : "memory");
    }
}

// LDG one W half-slab into regs: rows n0..n0+63, k-half index kh (units of 64 k)
__device__ __forceinline__ void ldg_w(int4* wq, const int4* __restrict__ W,
                                      int n0, int kh, int tid) {
    const size_t wrow = (size_t)K_DIM / 4;
#pragma unroll
    for (int i = 0; i < 4; i++) {
        int li = i * 256 + tid, r = li >> 4, cg = li & 15;
        wq[i] = W[(size_t)(n0 + r) * wrow + kh * 16 + cg];
    }
}

// issue full A slab (both k-halves) via cp.async into a stage; one commit group
__device__ __forceinline__ void issue_A(const __half* Abase, int kbase,
                                        uint32_t dst, int tid) {
#pragma unroll
    for (int h = 0; h < 2; h++) {
#pragma unroll
        for (int i = 0; i < 4; i++) {
            int li = i * 256 + tid, r = li >> 3, c = li & 7;
            const __half* src = Abase + (size_t)r * K_DIM + kbase + h * 64 + c * 8;
            uint32_t d = dst + h * A_HALF + SWZ(r * 128 + c * 16);
            asm volatile("cp.async.cg.shared.global [%0], [%1], 16;"
                         :: "r"(d), "l"(src));
        }
    }
    asm volatile("cp.async.commit_group;" ::: "memory");
}

__global__ void __launch_bounds__(THREADS, 2)
qlinear_hmma_kernel(const int4* __restrict__ W, const float* __restrict__ scale,
                    const float* __restrict__ bias, float* __restrict__ out) {
    extern __shared__ char smem_raw[];
    const uint32_t smem = (smem_u32(smem_raw) + 1023u) & ~1023u;

    const int tid  = threadIdx.x;
    const int wid  = tid >> 5;
    const int lane = tid & 31;
    const int wm   = wid >> 1;          // 0..3 : 32-row M strip
    const int wn   = wid & 1;           // 0..1 : 32-col N strip
    const int m0   = blockIdx.x * MTILE;    // m fastest -> weight L2 reuse
    const int n0   = blockIdx.y * NTILE;

    const __half* Abase = g_A + (size_t)m0 * K_DIM;

    float acc[2][4][4];
#pragma unroll
    for (int i = 0; i < 2; i++)
#pragma unroll
        for (int j = 0; j < 4; j++)
#pragma unroll
            for (int e = 0; e < 4; e++) acc[i][j][e] = 0.f;

    int4 wq[4];   // one W k-half in flight

    // ---- prologue: stage 0 = slab 0, wq = W(1).half0 ---------------------
    ldg_w(wq, W, n0, 0, tid);                 // W(0).h0
    issue_A(Abase, 0, smem, tid);             // A(0) both halves
    dequant_sts(wq, smem + W_BASE, tid);      // -> stage0 W panel0
    ldg_w(wq, W, n0, 1, tid);                 // W(0).h1
    dequant_sts(wq, smem + W_BASE + W_HALF, tid);
    ldg_w(wq, W, n0, 2, tid);                 // W(1).h0 (consumed at s=0)

    // ---- main loop ------------------------------------------------------
#pragma unroll 1
    for (int s = 0; s < NSLABS; s++) {
        const int p = s & 1;
        const uint32_t a_sm = smem + p * STAGE_BYTES;
        const uint32_t w_sm = a_sm + W_BASE;
        const uint32_t nxt  = smem + (p ^ 1) * STAGE_BYTES;

        asm volatile("cp.async.wait_group 0;" ::: "memory");   // A(s) arrived
        __syncthreads();   // stage p ready; stage p^1 free (readers of s-1 done)

        if (s + 1 < NSLABS) {
            issue_A(Abase, (s + 1) * KSLAB, nxt, tid);       // A(s+1)
            dequant_sts(wq, nxt + W_BASE, tid);              // W(s+1).h0
            ldg_w(wq, W, n0, (s + 1) * 2 + 1, tid);          // W(s+1).h1
        }

        // compute k-half 0 (panel 0)
#pragma unroll
        for (int ks = 0; ks < 4; ks++) {
            const int chunk = ks * 2 + (lane >> 4);
            uint32_t a[2][4];
#pragma unroll
            for (int mt = 0; mt < 2; mt++) {
                int row = wm * 32 + mt * 16 + (lane & 15);
                ldsm_x4(a[mt][0], a[mt][1], a[mt][2], a[mt][3],
                        a_sm + SWZ(row * 128 + chunk * 16));
            }
            uint32_t b[4][2];
#pragma unroll
            for (int j = 0; j < 2; j++) {
                int row = wn * 32 + j * 16 + (lane & 15);
                uint32_t t0, t1, t2, t3;
                ldsm_x4(t0, t1, t2, t3, w_sm + SWZ(row * 128 + chunk * 16));
                b[j * 2 + 0][0] = t0;  b[j * 2 + 1][0] = t1;
                b[j * 2 + 0][1] = t2;  b[j * 2 + 1][1] = t3;
            }
#pragma unroll
            for (int mt = 0; mt < 2; mt++)
#pragma unroll
                for (int nt = 0; nt < 4; nt++)
                    mma16816(acc[mt][nt], a[mt], b[nt][0], b[nt][1]);
        }

        if (s + 1 < NSLABS) {
            dequant_sts(wq, nxt + W_BASE + W_HALF, tid);     // W(s+1).h1
            if (s + 2 < NSLABS)
                ldg_w(wq, W, n0, (s + 2) * 2, tid);          // W(s+2).h0
        }

        // compute k-half 1 (panel 1)
#pragma unroll
        for (int ks = 0; ks < 4; ks++) {
            const int chunk = ks * 2 + (lane >> 4);
            uint32_t a[2][4];
#pragma unroll
            for (int mt = 0; mt < 2; mt++) {
                int row = wm * 32 + mt * 16 + (lane & 15);
                ldsm_x4(a[mt][0], a[mt][1], a[mt][2], a[mt][3],
                        a_sm + A_HALF + SWZ(row * 128 + chunk * 16));
            }
            uint32_t b[4][2];
#pragma unroll
            for (int j = 0; j < 2; j++) {
                int row = wn * 32 + j * 16 + (lane & 15);
                uint32_t t0, t1, t2, t3;
                ldsm_x4(t0, t1, t2, t3, w_sm + W_HALF + SWZ(row * 128 + chunk * 16));
                b[j * 2 + 0][0] = t0;  b[j * 2 + 1][0] = t1;
                b[j * 2 + 0][1] = t2;  b[j * 2 + 1][1] = t3;
            }
#pragma unroll
            for (int mt = 0; mt < 2; mt++)
#pragma unroll
                for (int nt = 0; nt < 4; nt++)
                    mma16816(acc[mt][nt], a[mt], b[nt][0], b[nt][1]);
        }
    }

    // ---- epilogue: scale*acc + bias -> out ------------------------------
    const int ncb = n0 + wn * 32;
    float sc[4][2], bs[4][2];
#pragma unroll
    for (int nt = 0; nt < 4; nt++) {
#pragma unroll
        for (int e = 0; e < 2; e++) {
            int col = ncb + nt * 8 + (lane & 3) * 2 + e;
            sc[nt][e] = __ldg(&scale[col]);
            bs[nt][e] = __ldg(&bias[col]);
        }
    }
#pragma unroll
    for (int mt = 0; mt < 2; mt++) {
        int row = m0 + wm * 32 + mt * 16 + (lane >> 2);
#pragma unroll
        for (int nt = 0; nt < 4; nt++) {
            int col = ncb + nt * 8 + (lane & 3) * 2;
            float2 v0, v1;
            v0.x = acc[mt][nt][0] * sc[nt][0] + bs[nt][0];
            v0.y = acc[mt][nt][1] * sc[nt][1] + bs[nt][1];
            v1.x = acc[mt][nt][2] * sc[nt][0] + bs[nt][0];
            v1.y = acc[mt][nt][3] * sc[nt][1] + bs[nt][1];
            *reinterpret_cast<float2*>(out + (size_t)row * N_DIM + col)       = v0;
            *reinterpret_cast<float2*>(out + (size_t)(row + 8) * N_DIM + col) = v1;
        }
    }
}

// ------------------------------------------------------------------ launch
extern "C" void kernel_launch(void* const* d_in, const int* in_sizes, int n_in,
                              void* d_out, int out_size) {
    (void)in_sizes; (void)n_in; (void)out_size;
    const float* input = (const float*)d_in[0];
    const int4*  W     = (const int4*)d_in[1];
    const float* scale = (const float*)d_in[2];
    const float* bias  = (const float*)d_in[3];
    float* out = (float*)d_out;

    convert_A_kernel<<<(M_DIM * K_DIM / 4 + 255) / 256, 256>>>(input);

    cudaFuncSetAttribute(qlinear_hmma_kernel,
                         cudaFuncAttributeMaxDynamicSharedMemorySize, SMEM_BYTES);
    dim3 grid(M_DIM / MTILE, N_DIM / NTILE);   // m fastest: weight L2 reuse
    qlinear_hmma_kernel<<<grid, THREADS, SMEM_BYTES>>>(W, scale, bias, out);
}